// round 10
// baseline (speedup 1.0000x reference)
#include <cuda_runtime.h>
#include <cuda_fp16.h>
#include <math.h>
#include <stdint.h>

#define Bc   32
#define DIM  256
#define Hc   56
#define Wc   56
#define HWc  (Hc*Wc)          // 3136
#define TOK  (Bc*HWc)         // 100352
#define HID  1024

typedef __half f16;

// ---------------- scratch (device globals; no runtime allocation) ------------
__device__ f16 g_conv[(size_t)Bc*DIM*HWc];                   // conv out, NCHW f16
__device__ __align__(256) f16 g_a  [(size_t)TOK*DIM];        // LN out (fp16)
__device__ __align__(256) f16 g_h  [(size_t)TOK*HID];        // hidden (fp16)
__device__ __align__(256) f16 g_w1t[(size_t)HID*DIM];        // w1^T [N=1024][K=256]
__device__ __align__(256) f16 g_w2t[(size_t)DIM*HID];        // w2^T [N=256][K=1024]

// ---------------- asm primitives (base sm_103, no 'a' features) --------------
__device__ __forceinline__ uint32_t smem_u32(const void* p) {
    uint32_t a;
    asm("{ .reg .u64 t; cvta.to.shared.u64 t, %1; cvt.u32.u64 %0, t; }"
        : "=r"(a) : "l"(p));
    return a;
}
#define CP16(dst, src) \
    asm volatile("cp.async.cg.shared.global [%0], [%1], 16;" \
                 :: "r"(dst), "l"(src) : "memory")
#define CP_COMMIT() asm volatile("cp.async.commit_group;" ::: "memory")
#define CP_WAIT(n)  asm volatile("cp.async.wait_group %0;" :: "n"(n) : "memory")
#define LDSM4(r, addr) \
    asm volatile("ldmatrix.sync.aligned.m8n8.x4.shared.b16 {%0,%1,%2,%3}, [%4];" \
                 : "=r"((r)[0]), "=r"((r)[1]), "=r"((r)[2]), "=r"((r)[3]) \
                 : "r"(addr))
#define MMA16816(d, a, b0v, b1v) \
    asm volatile("mma.sync.aligned.m16n8k16.row.col.f32.f16.f16.f32 " \
                 "{%0,%1,%2,%3}, {%4,%5,%6,%7}, {%8,%9}, {%0,%1,%2,%3};" \
                 : "+f"((d)[0]), "+f"((d)[1]), "+f"((d)[2]), "+f"((d)[3]) \
                 : "r"((a)[0]), "r"((a)[1]), "r"((a)[2]), "r"((a)[3]), \
                   "r"(b0v), "r"(b1v))

__device__ __forceinline__ uint32_t sw128(uint32_t off) {
    return off ^ ((off >> 3) & 0x70);
}
__device__ __forceinline__ uint32_t pack2(f16 a, f16 b) {
    return (uint32_t)*(uint16_t*)&a | ((uint32_t)*(uint16_t*)&b << 16);
}

// Fast exact-GELU: Abramowitz-Stegun 7.1.26 erf (|abs err| <= 1.5e-7).
__device__ __forceinline__ float gelu_fast(float x) {
    const float t = fabsf(x) * 0.70710678118654752f;
    const float u = __fdividef(1.f, fmaf(0.3275911f, t, 1.f));
    float p = fmaf(1.061405429f, u, -1.453152027f);
    p = fmaf(p, u, 1.421413741f);
    p = fmaf(p, u, -0.284496736f);
    p = fmaf(p, u, 0.254829592f);
    p = p * u;
    const float e  = __expf(-t * t);
    const float er = copysignf(fmaf(-p, e, 1.f), x);
    return 0.5f * x * (1.f + er);
}

// ------- 1) depthwise 7x7 conv + bias: one block per (b,c) plane -------------
__global__ __launch_bounds__(256) void dwconv_kernel(
    const float* __restrict__ x, const float* __restrict__ cw,
    const float* __restrict__ cb)
{
    const int bc = blockIdx.x;            // b*DIM + c
    const int c  = bc & (DIM-1);

    __shared__ float sx[62][64];          // rows -3..58, cols -3..60 (pad 64)
    __shared__ float sw[49];

    const float* xp = x + (size_t)bc*HWc;
    const int t = threadIdx.x;
    if (t < 49) sw[t] = cw[c*49 + t];

    for (int i = t; i < 62*64; i += 256) {
        const int r = i >> 6, col = i & 63;
        const int gr = r - 3, gc = col - 3;
        float v = 0.f;
        if (gr >= 0 && gr < Hc && gc >= 0 && gc < Wc)
            v = xp[gr*Wc + gc];
        sx[r][col] = v;
    }
    __syncthreads();

    const float bias = cb[c];
    f16* op = g_conv + (size_t)bc*HWc;
    const int col = t & 63, r0 = t >> 6;  // 4 rows x 64 cols per iteration
    if (col < Wc) {
        #pragma unroll
        for (int rr = r0; rr < Hc; rr += 4) {
            float acc = bias;
            #pragma unroll
            for (int ki = 0; ki < 7; ki++)
                #pragma unroll
                for (int kj = 0; kj < 7; kj++)
                    acc = fmaf(sx[rr+ki][col+kj], sw[ki*7+kj], acc);
            op[rr*Wc + col] = __float2half_rn(acc);
        }
    }
}

// ------- 2) LayerNorm over channels + NCHW->NHWC, emit fp16 ------------------
__global__ __launch_bounds__(256) void ln_kernel(
    const float* __restrict__ gamma, const float* __restrict__ beta)
{
    int tile = blockIdx.x;
    int b    = tile / (HWc/32);
    int pixbase = (tile % (HWc/32)) * 32;

    __shared__ float s[DIM][33];
    __shared__ float psum[8][32], psq[8][32];
    __shared__ float mu_s[32], rs_s[32];

    int t = threadIdx.x;
    int p = t & 31, gi = t >> 5;

    const f16* base = g_conv + (size_t)b*DIM*HWc + pixbase;
    #pragma unroll
    for (int cc = 0; cc < 32; cc++) {
        int c = gi*32 + cc;
        s[c][p] = __half2float(base[(size_t)c*HWc + p]);
    }
    __syncthreads();

    float sum = 0.f, sq = 0.f;
    #pragma unroll
    for (int cc = 0; cc < 32; cc++) {
        float v = s[gi*32+cc][p];
        sum += v; sq = fmaf(v, v, sq);
    }
    psum[gi][p] = sum; psq[gi][p] = sq;
    __syncthreads();

    if (gi == 0) {
        float S = 0.f, Q = 0.f;
        #pragma unroll
        for (int k = 0; k < 8; k++) { S += psum[k][p]; Q += psq[k][p]; }
        float mu  = S * (1.f/DIM);
        float var = Q * (1.f/DIM) - mu*mu;
        mu_s[p] = mu;
        rs_s[p] = rsqrtf(var + 1e-6f);
    }
    __syncthreads();

    size_t tokbase = (size_t)b*HWc + pixbase;
    for (int i = t; i < 32*128; i += 256) {
        int pp = i >> 7, c2 = (i & 127) * 2;
        float mu = mu_s[pp], rs = rs_s[pp];
        float v0 = (s[c2  ][pp] - mu) * rs * gamma[c2  ] + beta[c2  ];
        float v1 = (s[c2+1][pp] - mu) * rs * gamma[c2+1] + beta[c2+1];
        *(uint32_t*)(g_a + (tokbase + pp)*DIM + c2) =
            pack2(__float2half_rn(v0), __float2half_rn(v1));
    }
}

// ------- 2b) transpose weights to fp16: w1[K,N]->w1t[N,K], w2 likewise -------
__global__ __launch_bounds__(256) void prep_w_kernel(
    const float* __restrict__ w1, const float* __restrict__ w2)
{
    int idx = blockIdx.x * 256 + threadIdx.x;
    if (idx < HID*DIM) {                       // w1t [n=1024][k=256]
        int n = idx >> 8, k = idx & 255;
        g_w1t[idx] = __float2half_rn(w1[(size_t)k*HID + n]);
    } else {                                   // w2t [n=256][k=1024]
        int j = idx - HID*DIM;
        int n = j >> 10, k = j & 1023;
        g_w2t[j] = __float2half_rn(w2[(size_t)k*DIM + n]);
    }
}

// ---------------- 3/4) HMMA fp16 GEMM, ks-software-pipelined ------------------
// CTA 128x128, BK=64, 256 threads, 2 CTAs/SM, 3-stage cp.async pipeline.
// Fragments double-buffered across ks: LDSM(ks+1) overlaps MMA(ks), keeping
// smem crossbar and tensor pipe concurrently busy (breaks phase coherence).
// Address identities (SW128): row/chunk deltas live above swizzle bits, so
// all LDSM/CP offsets = one base + immediates; k-step = base ^ (32*ks).
#define STAGE  32768
#define GSMEM  (3*STAGE)     // 98304

// 4 A-fragments (64 rows span, 16-row strides = +2048B each)
#define LDSMA(dst, base) do {            \
    LDSM4((dst)[0], (base));             \
    LDSM4((dst)[1], (base) + 2048);      \
    LDSM4((dst)[2], (base) + 4096);      \
    LDSM4((dst)[3], (base) + 6144); } while (0)
// 4 B-fragments from 2 LDSM4 (16-row stride = +2048B)
#define LDSMB(dst, base) do {            \
    uint32_t _r[4];                      \
    LDSM4(_r, (base));                   \
    (dst)[0][0]=_r[0]; (dst)[0][1]=_r[1]; (dst)[1][0]=_r[2]; (dst)[1][1]=_r[3]; \
    LDSM4(_r, (base) + 2048);            \
    (dst)[2][0]=_r[0]; (dst)[2][1]=_r[1]; (dst)[3][0]=_r[2]; (dst)[3][1]=_r[3]; } while (0)

template<int KTOT, int MODE>
__global__ __launch_bounds__(256, 2) void hgemm_kernel(
    const f16* __restrict__ A, const f16* __restrict__ Bw,
    const float* __restrict__ bias,
    f16* __restrict__ Oh, float* __restrict__ Of)
{
    extern __shared__ char smem[];
    __shared__ float sbias[128];

    const int tid  = threadIdx.x;
    const int wid  = tid >> 5, lane = tid & 31;
    const int warpM = wid >> 2, warpN = wid & 3;        // 2 x 4
    const int n0 = blockIdx.x * 128;
    const size_t m0 = (size_t)blockIdx.y * 128;

    if (tid < 128) sbias[tid] = bias[n0 + tid];

    const uint32_t sb = smem_u32(smem);

    // ---- producer: single base offsets (it-delta = +4096 smem, +32*KTOT gmem)
    const f16* Abase = A + m0 * KTOT;
    const f16* Bbase = Bw + (size_t)n0 * KTOT;
    const uint32_t soff0 = sw128((uint32_t)((tid >> 3)*128 + (tid & 7)*16));
    const uint32_t goff0 = (uint32_t)(tid >> 3) * (uint32_t)KTOT + (tid & 7)*8;

    auto load_stage = [&](int c, int s) {
        const uint32_t st = sb + s * STAGE + soff0;
        const f16* ga = Abase + goff0 + (uint32_t)c * 64;
        const f16* gb = Bbase + goff0 + (uint32_t)c * 64;
        #pragma unroll
        for (int it = 0; it < 4; it++) {
            CP16(st + it*4096,         ga + it*32*KTOT);
            CP16(st + 16384 + it*4096, gb + it*32*KTOT);
        }
    };

    // ---- consumer: single A and B base offsets -------------------------------
    const int j  = lane >> 3, lr = lane & 7;
    const uint32_t mask = (uint32_t)lr << 4;
    const uint32_t aoff0 = (uint32_t)(warpM*64 + ((j & 1) << 3) + lr)*128
                         + (((uint32_t)(j >> 1) << 4) ^ mask);
    const uint32_t boff0 = 16384
                         + (uint32_t)(warpN*32 + ((j >> 1) << 3) + lr)*128
                         + (((uint32_t)(j & 1) << 4) ^ mask);

    float acc[4][4][4] = {};
    uint32_t ah[2][4][4], bh[2][4][2];

    const int NC = KTOT / 64;
    load_stage(0, 0); CP_COMMIT();
    if (NC > 1) { load_stage(1, 1); CP_COMMIT(); }

    int s_use = 0, s_load = 2;
    #pragma unroll 1
    for (int c = 0; c < NC; c++) {
        if (c + 1 < NC) { CP_WAIT(1); } else { CP_WAIT(0); }
        __syncthreads();

        const uint32_t st = sb + s_use * STAGE;
        if (++s_use == 3) s_use = 0;
        const uint32_t a0 = st + aoff0, b0 = st + boff0;

        // prefetch ks=0 fragments, then issue next stage's cp.async
        LDSMB(bh[0], b0);
        LDSMA(ah[0], a0);
        if (c + 2 < NC) {
            load_stage(c + 2, s_load); CP_COMMIT();
            if (++s_load == 3) s_load = 0;
        }

        #pragma unroll
        for (int ks = 0; ks < 4; ks++) {
            const int cur = ks & 1, nxt = cur ^ 1;
            if (ks < 3) {                          // LDSM(ks+1) overlaps MMA(ks)
                const uint32_t kx = 32u * (ks + 1);
                LDSMB(bh[nxt], b0 ^ kx);
                LDSMA(ah[nxt], a0 ^ kx);
            }
            #pragma unroll
            for (int mt = 0; mt < 4; mt++)
                #pragma unroll
                for (int nt = 0; nt < 4; nt++)
                    MMA16816(acc[mt][nt], ah[cur][mt],
                             bh[cur][nt][0], bh[cur][nt][1]);
        }
    }

    // ------------------------- epilogue -------------------------------------
    const int mlane = lane >> 2;         // row within 8-row group
    const int nlane = (lane & 3) * 2;    // even col pair

    if (MODE == 1) {
        #pragma unroll
        for (int mt = 0; mt < 4; mt++) {
            const size_t mA = m0 + warpM*64 + mt*16 + mlane;
            #pragma unroll
            for (int nt = 0; nt < 4; nt++) {
                const int nc = warpN*32 + nt*8 + nlane;
                const float b0 = sbias[nc], b1 = sbias[nc + 1];
                #pragma unroll
                for (int half = 0; half < 2; half++) {
                    float v0 = gelu_fast(acc[mt][nt][half*2]     + b0);
                    float v1 = gelu_fast(acc[mt][nt][half*2 + 1] + b1);
                    size_t o = (mA + half*8) * (size_t)HID + n0 + nc;
                    *(uint32_t*)(Oh + o) = pack2(__float2half_rn(v0),
                                                 __float2half_rn(v1));
                }
            }
        }
    } else {
        __syncthreads();                   // stage smem free for reuse
        float* sf = (float*)smem;          // [128 n][132 m] fp32 transpose tile
        #pragma unroll
        for (int mt = 0; mt < 4; mt++) {
            const int mA = warpM*64 + mt*16 + mlane;
            #pragma unroll
            for (int nt = 0; nt < 4; nt++) {
                const int nc = warpN*32 + nt*8 + nlane;
                sf[(nc    )*132 + mA    ] = acc[mt][nt][0];
                sf[(nc + 1)*132 + mA    ] = acc[mt][nt][1];
                sf[(nc    )*132 + mA + 8] = acc[mt][nt][2];
                sf[(nc + 1)*132 + mA + 8] = acc[mt][nt][3];
            }
        }
        __syncthreads();
        #pragma unroll 4
        for (int i = tid; i < 128*128; i += 256) {
            const int n = i >> 7, mm = i & 127;
            const int tok = (int)m0 + mm;
            const int b = tok / HWc, pix = tok % HWc;
            Of[((size_t)b*DIM + n0 + n)*HWc + pix] = sf[n*132 + mm] + sbias[n];
        }
    }
}

// ---------------- launch -----------------------------------------------------
extern "C" void kernel_launch(void* const* d_in, const int* in_sizes, int n_in,
                              void* d_out, int out_size)
{
    const float* x      = (const float*)d_in[0];
    const float* conv_w = (const float*)d_in[1];
    const float* conv_b = (const float*)d_in[2];
    const float* ln_g   = (const float*)d_in[3];
    const float* ln_b   = (const float*)d_in[4];
    const float* w1     = (const float*)d_in[5];
    const float* b1     = (const float*)d_in[6];
    const float* w2     = (const float*)d_in[7];
    const float* b2     = (const float*)d_in[8];
    float* out = (float*)d_out;

    f16 *p_a, *p_h, *p_w1t, *p_w2t;
    cudaGetSymbolAddress((void**)&p_a,   g_a);
    cudaGetSymbolAddress((void**)&p_h,   g_h);
    cudaGetSymbolAddress((void**)&p_w1t, g_w1t);
    cudaGetSymbolAddress((void**)&p_w2t, g_w2t);

    cudaFuncSetAttribute((const void*)hgemm_kernel<DIM, 1>,
                         cudaFuncAttributeMaxDynamicSharedMemorySize, GSMEM);
    cudaFuncSetAttribute((const void*)hgemm_kernel<HID, 2>,
                         cudaFuncAttributeMaxDynamicSharedMemorySize, GSMEM);

    dwconv_kernel<<<Bc*DIM, 256>>>(x, conv_w, conv_b);
    ln_kernel<<<TOK/32, 256>>>(ln_g, ln_b);
    prep_w_kernel<<<(2*HID*DIM)/256, 256>>>(w1, w2);

    // GEMM1: [TOK,256] x w1t -> GELU -> h (fp16)
    hgemm_kernel<DIM, 1><<<dim3(HID/128, TOK/128), 256, GSMEM>>>(
        p_a, p_w1t, b1, p_h, nullptr);
    // GEMM2: [TOK,1024] x w2t -> +b2 -> fp32 NCHW out
    hgemm_kernel<HID, 2><<<dim3(DIM/128, TOK/128), 256, GSMEM>>>(
        p_h, p_w2t, b2, nullptr, out);
}